// round 7
// baseline (speedup 1.0000x reference)
#include <cuda_runtime.h>
#include <cuda_fp16.h>
#include <cstdint>

#define L_SEQ 4096
#define D_DIM 1024
#define BATCH 4
#define M_TOT 16384

// scratch
__device__ float  g_uproj[(size_t)M_TOT * D_DIM];   // 64 MB
// tiled fp16: [tile][kc][row 128][64B], 8KB per (tile,kc) block, swizzled
__device__ __align__(16) __half g_Uh[(size_t)M_TOT * D_DIM];  // 32 MB
__device__ __align__(16) __half g_Wh[(size_t)D_DIM * D_DIM];  // 2 MB
// per-GEMM-tile done flags [tile_m(128)][tile_n(8)]
__device__ int g_flag[1024];

__device__ __forceinline__ float silu_f(float x) {
    return x / (1.0f + __expf(-x));
}

__device__ __forceinline__ uint32_t smem_u32(const void* p) {
    uint32_t a;
    asm("{ .reg .u64 t; cvta.to.shared.u64 t, %1; cvt.u32.u64 %0, t; }"
        : "=r"(a) : "l"(p));
    return a;
}

// ---------------------------------------------------------------------------
// Kernel 0: convert U, Wp to fp16 in tiled+swizzled layout; zero flags.
// ---------------------------------------------------------------------------
#define NCH_U (M_TOT * 128)     // 16B-chunks for U: 16384 rows * 128
#define NCH_W (D_DIM * 128)

__global__ void __launch_bounds__(256)
convert_kernel(const float* __restrict__ U, const float* __restrict__ Wp)
{
    if (blockIdx.x == 0) {
        for (int i = threadIdx.x; i < 1024; i += 256) g_flag[i] = 0;
    }
    const int stride = gridDim.x * blockDim.x;
    for (int i = blockIdx.x * blockDim.x + threadIdx.x;
         i < NCH_U + NCH_W; i += stride) {
        int j; const float* src; __half* dstbase;
        if (i < NCH_U) { j = i; src = U; dstbase = g_Uh; }
        else           { j = i - NCH_U; src = Wp; dstbase = g_Wh; }
        const int c    = j & 3;
        const int r    = (j >> 2) & 127;
        const int kc   = (j >> 9) & 31;
        const int tile = j >> 14;
        const int m    = tile * 128 + r;
        const float4* s = (const float4*)(src + (size_t)m * D_DIM + kc * 32 + c * 8);
        float4 v0 = s[0], v1 = s[1];
        __half2 h0 = __floats2half2_rn(v0.x, v0.y);
        __half2 h1 = __floats2half2_rn(v0.z, v0.w);
        __half2 h2 = __floats2half2_rn(v1.x, v1.y);
        __half2 h3 = __floats2half2_rn(v1.z, v1.w);
        uint4 o;
        o.x = *(const uint32_t*)&h0; o.y = *(const uint32_t*)&h1;
        o.z = *(const uint32_t*)&h2; o.w = *(const uint32_t*)&h3;
        const int csw = c ^ ((r >> 1) & 3);
        const size_t half_off = ((size_t)(tile * 32 + kc) << 12)
                              + (size_t)r * 32 + csw * 8;
        *(uint4*)(dstbase + half_off) = o;
    }
}

// ---------------------------------------------------------------------------
// Heterogeneous kernel: bids [0,1024) = GEMM 128x128 tiles (tensor pipe),
// bids [1024,3072) = conv CTAs (fma/lds pipes). GEMM signals per-tile flags;
// conv spins (acquire) then multiplies uproj inline and writes final out.
// ---------------------------------------------------------------------------
#define GEMM_CTAS 1024
#define CONV_CTAS 2048
#define STAGE_SZ 16384          // A 8KB + B 8KB
#define SM_MBAR  49152          // 3 mbarriers
#define HET_SMEM 98304          // conv needs 96KB

#define MBAR_INIT(mbar, cnt) \
    asm volatile("mbarrier.init.shared.b64 [%0], %1;" \
                 :: "r"((uint32_t)(mbar)), "r"((uint32_t)(cnt)) : "memory")
#define MBAR_EXPECT_TX(mbar, bytes) \
    asm volatile("mbarrier.arrive.expect_tx.shared.b64 _, [%0], %1;" \
                 :: "r"((uint32_t)(mbar)), "r"((uint32_t)(bytes)) : "memory")
#define MBAR_WAIT(mbar, ph) do { \
    uint32_t _m = (uint32_t)(mbar); uint32_t _p = (uint32_t)(ph); \
    asm volatile("{\n\t.reg .pred P1;\n\t" \
        "W_%=:\n\t" \
        "mbarrier.try_wait.parity.acquire.cta.shared::cta.b64 P1, [%0], %1, 0x989680;\n\t" \
        "@P1 bra.uni D_%=;\n\t" \
        "bra.uni W_%=;\n\t" \
        "D_%=:\n\t}" :: "r"(_m), "r"(_p) : "memory"); \
} while (0)

__device__ __forceinline__ void bulk_cp(uint32_t dst, const void* src,
                                        uint32_t bytes, uint32_t mbar) {
    asm volatile(
        "cp.async.bulk.shared::cta.global.mbarrier::complete_tx::bytes "
        "[%0], [%1], %2, [%3];"
        :: "r"(dst), "l"(__cvta_generic_to_global(src)), "r"(bytes), "r"(mbar)
        : "memory");
}

__device__ __forceinline__ void ldmatrix4(uint32_t* r, uint32_t addr) {
    asm volatile("ldmatrix.sync.aligned.m8n8.x4.shared.b16 {%0,%1,%2,%3}, [%4];"
                 : "=r"(r[0]), "=r"(r[1]), "=r"(r[2]), "=r"(r[3]) : "r"(addr));
}

__device__ __forceinline__ void mma16816(float* c, const uint32_t* a,
                                         uint32_t b0, uint32_t b1) {
    asm volatile(
        "mma.sync.aligned.m16n8k16.row.col.f32.f16.f16.f32 "
        "{%0,%1,%2,%3}, {%4,%5,%6,%7}, {%8,%9}, {%0,%1,%2,%3};"
        : "+f"(c[0]), "+f"(c[1]), "+f"(c[2]), "+f"(c[3])
        : "r"(a[0]), "r"(a[1]), "r"(a[2]), "r"(a[3]), "r"(b0), "r"(b1));
}

// conv geometry
#define CLT 128
#define CP  32
#define CHROWS (CLT + 128)

typedef unsigned long long ull;

__device__ __forceinline__ void ffma2(ull& d, ull a, ull b) {
    asm("fma.rn.f32x2 %0, %1, %2, %0;" : "+l"(d) : "l"(a), "l"(b));
}
__device__ __forceinline__ float2 unpack2(ull v) {
    float2 r;
    asm("mov.b64 {%0,%1}, %2;" : "=f"(r.x), "=f"(r.y) : "l"(v));
    return r;
}

__device__ void gemm_part(char* sm, const float* __restrict__ bp)
{
    const uint32_t sbase = smem_u32(sm);
    const uint32_t mb    = sbase + SM_MBAR;
    const int tid  = threadIdx.x;
    const int lane = tid & 31;
    const int warp = tid >> 5;
    const int wm = warp & 3;      // 0..3  M 32-row slab
    const int wn = warp >> 2;     // 0..1  N 64-col slab

    const int t      = blockIdx.x;
    const int tile_m = t >> 3;
    const int tile_n = t & 7;
    const int m0 = tile_m * 128;
    const int n0 = tile_n * 128;

    float c[2][8][4];
    #pragma unroll
    for (int i = 0; i < 2; i++)
        #pragma unroll
        for (int j = 0; j < 8; j++)
            #pragma unroll
            for (int r = 0; r < 4; r++) c[i][j][r] = 0.0f;

    // precompute per-lane ldmatrix offsets (swizzled, row stride 64B)
    int offA[2][2], offB[4][2];
    {
        const int c0a = (lane >> 4) & 1;
        const int c0b = (lane >> 3) & 1;
        #pragma unroll
        for (int mt = 0; mt < 2; mt++) {
            int rA = wm * 32 + mt * 16 + (lane & 7) + ((lane >> 3) & 1) * 8;
            int sw = (rA >> 1) & 3;
            #pragma unroll
            for (int kk = 0; kk < 2; kk++)
                offA[mt][kk] = rA * 64 + (((c0a | (kk << 1)) ^ sw) << 4);
        }
        #pragma unroll
        for (int bh = 0; bh < 4; bh++) {
            int rB = wn * 64 + bh * 16 + (lane & 7) + ((lane >> 4) & 1) * 8;
            int sw = (rB >> 1) & 3;
            #pragma unroll
            for (int kk = 0; kk < 2; kk++)
                offB[bh][kk] = 8192 + rB * 64 + (((c0b | (kk << 1)) ^ sw) << 4);
        }
    }

    const char* Abase = (const char*)g_Uh + (size_t)tile_m * 32 * 8192;
    const char* Bbase = (const char*)g_Wh + (size_t)tile_n * 32 * 8192;

    if (tid == 0) {
        MBAR_INIT(mb + 0, 1);
        MBAR_INIT(mb + 8, 1);
        MBAR_INIT(mb + 16, 1);
        asm volatile("fence.proxy.async.shared::cta;" ::: "memory");
        #pragma unroll
        for (int k0 = 0; k0 < 2; k0++) {
            MBAR_EXPECT_TX(mb + k0 * 8, STAGE_SZ);
            bulk_cp(sbase + k0 * STAGE_SZ,        Abase + (size_t)k0 * 8192,
                    8192, mb + k0 * 8);
            bulk_cp(sbase + k0 * STAGE_SZ + 8192, Bbase + (size_t)k0 * 8192,
                    8192, mb + k0 * 8);
        }
    }
    __syncthreads();

    for (int kc = 0; kc < 32; kc++) {
        const int s = kc % 3;
        MBAR_WAIT(mb + s * 8, (kc / 3) & 1);
        __syncthreads();
        if (tid == 0 && kc + 2 < 32) {
            const int slot = (kc + 2) % 3;
            asm volatile("fence.proxy.async.shared::cta;" ::: "memory");
            MBAR_EXPECT_TX(mb + slot * 8, STAGE_SZ);
            bulk_cp(sbase + slot * STAGE_SZ,        Abase + (size_t)(kc + 2) * 8192,
                    8192, mb + slot * 8);
            bulk_cp(sbase + slot * STAGE_SZ + 8192, Bbase + (size_t)(kc + 2) * 8192,
                    8192, mb + slot * 8);
        }

        const uint32_t stage = sbase + s * STAGE_SZ;
        #pragma unroll
        for (int kk = 0; kk < 2; kk++) {
            uint32_t ar[2][4];
            #pragma unroll
            for (int mt = 0; mt < 2; mt++)
                ldmatrix4(ar[mt], stage + offA[mt][kk]);
            #pragma unroll
            for (int bh = 0; bh < 4; bh++) {
                uint32_t br[4];
                ldmatrix4(br, stage + offB[bh][kk]);
                #pragma unroll
                for (int mt = 0; mt < 2; mt++) {
                    mma16816(c[mt][2 * bh + 0], ar[mt], br[0], br[1]);
                    mma16816(c[mt][2 * bh + 1], ar[mt], br[2], br[3]);
                }
            }
        }
    }

    const int g  = lane >> 2;
    const int tq = lane & 3;
    #pragma unroll
    for (int mt = 0; mt < 2; mt++) {
        const int row = m0 + wm * 32 + mt * 16 + g;
        #pragma unroll
        for (int nt = 0; nt < 8; nt++) {
            const int col = n0 + wn * 64 + nt * 8 + tq * 2;
            float2 bb = *(const float2*)(bp + col);
            float2 v0 = make_float2(silu_f(c[mt][nt][0] + bb.x),
                                    silu_f(c[mt][nt][1] + bb.y));
            float2 v1 = make_float2(silu_f(c[mt][nt][2] + bb.x),
                                    silu_f(c[mt][nt][3] + bb.y));
            *(float2*)(g_uproj + (size_t)row * D_DIM + col)       = v0;
            *(float2*)(g_uproj + (size_t)(row + 8) * D_DIM + col) = v1;
        }
    }

    // signal tile done (release so conv's acquire sees uproj stores)
    __syncthreads();
    if (tid == 0) {
        int* f = &g_flag[tile_m * 8 + tile_n];
        asm volatile("st.release.gpu.global.b32 [%0], %1;"
                     :: "l"(f), "r"(1) : "memory");
    }
}

__device__ void conv_part(char* smc,
                          const float* __restrict__ u,
                          const float* __restrict__ w1,
                          const float* __restrict__ b1,
                          const float* __restrict__ w2,
                          const float* __restrict__ b2,
                          float* __restrict__ out)
{
    float2* h_s  = (float2*)smc;                              // [256][32]
    float2* w2_s = (float2*)(smc + CHROWS * CP * 8);          // [128][32]

    const int tid = threadIdx.x;
    const int c   = tid & 31;
    const int yy  = tid >> 5;

    // ordered by tile_m so consumption tracks GEMM production order
    const int idx    = blockIdx.x - GEMM_CTAS;
    const int tile_m = idx >> 4;          // 0..127
    const int chunk  = idx & 15;          // 64-channel group
    const int bb     = tile_m >> 5;
    const int lt     = tile_m & 31;
    const int tile_start = lt * CLT;
    const int p = chunk * CP + c;

    const float2* uf2  = (const float2*)u + (size_t)bb * L_SEQ * 512;
    const float2* w1f2 = (const float2*)w1;
    const float2* w2f2 = (const float2*)w2;

    #pragma unroll
    for (int i = tid; i < 128 * CP; i += 256) {
        int j = i >> 5, cc = i & 31;
        w2_s[j * CP + cc] = w2f2[(size_t)j * 512 + chunk * CP + cc];
    }

    const float2 w1_0 = w1f2[0 * 512 + p];
    const float2 w1_1 = w1f2[1 * 512 + p];
    const float2 w1_2 = w1f2[2 * 512 + p];
    const float2 b1c  = ((const float2*)b1)[p];

    for (int i = tid; i < CHROWS * CP; i += 256) {
        int hl = i >> 5;
        int l  = tile_start - 127 + hl;
        float2 hv = make_float2(0.0f, 0.0f);
        if (l >= 0 && l < L_SEQ) {
            float2 x2 = uf2[(size_t)l * 512 + p];
            float2 x1 = (l >= 1) ? uf2[(size_t)(l - 1) * 512 + p] : make_float2(0.f, 0.f);
            float2 x0 = (l >= 2) ? uf2[(size_t)(l - 2) * 512 + p] : make_float2(0.f, 0.f);
            float vx = fmaf(x0.x, w1_0.x, fmaf(x1.x, w1_1.x, fmaf(x2.x, w1_2.x, b1c.x)));
            float vy = fmaf(x0.y, w1_0.y, fmaf(x1.y, w1_1.y, fmaf(x2.y, w1_2.y, b1c.y)));
            hv.x = silu_f(vx);
            hv.y = silu_f(vy);
        }
        h_s[hl * CP + c] = hv;
    }
    __syncthreads();

    const int base = yy * 16;
    ull acc[16], win[16];
    #pragma unroll
    for (int r = 0; r < 16; r++) {
        acc[r] = 0ULL;
        win[r] = *(const ull*)&h_s[(base + r) * CP + c];
    }
    #pragma unroll 8
    for (int j = 0; j < 128; j++) {
        ull w = *(const ull*)&w2_s[j * CP + c];
        #pragma unroll
        for (int r = 0; r < 16; r++)
            ffma2(acc[r], win[(j + r) & 15], w);
        win[j & 15] = *(const ull*)&h_s[(base + j + 16) * CP + c];
    }

    // wait for the producing GEMM tile (usually already done)
    if (tid == 0) {
        const int* f = &g_flag[tile_m * 8 + (chunk >> 1)];
        int v;
        do {
            asm volatile("ld.acquire.gpu.global.b32 %0, [%1];"
                         : "=r"(v) : "l"(f) : "memory");
            if (!v) __nanosleep(128);
        } while (!v);
    }
    __syncthreads();

    const float2 b2c = ((const float2*)b2)[p];
    const float2* upf2 = (const float2*)g_uproj
                         + ((size_t)bb * L_SEQ + tile_start) * 512 + p;
    float2* opf2 = (float2*)out + ((size_t)bb * L_SEQ + tile_start) * 512 + p;

    #pragma unroll
    for (int r = 0; r < 16; r++) {
        float2 a  = unpack2(acc[r]);
        int lo    = base + r;
        float2 pr = upf2[(size_t)lo * 512];
        float2 y;
        y.x = (a.x + b2c.x) * pr.x;
        y.y = (a.y + b2c.y) * pr.y;
        opf2[(size_t)lo * 512] = y;
    }
}

__global__ void __launch_bounds__(256, 2)
hetero_kernel(const float* __restrict__ u,
              const float* __restrict__ w1,
              const float* __restrict__ b1,
              const float* __restrict__ w2,
              const float* __restrict__ b2,
              const float* __restrict__ bp,
              float* __restrict__ out)
{
    extern __shared__ __align__(128) char sm[];
    if (blockIdx.x < GEMM_CTAS)
        gemm_part(sm, bp);
    else
        conv_part(sm, u, w1, b1, w2, b2, out);
}

// ---------------------------------------------------------------------------
extern "C" void kernel_launch(void* const* d_in, const int* in_sizes, int n_in,
                              void* d_out, int out_size)
{
    const float* u  = (const float*)d_in[0];
    const float* w1 = (const float*)d_in[1];
    const float* b1 = (const float*)d_in[2];
    const float* w2 = (const float*)d_in[3];
    const float* b2 = (const float*)d_in[4];
    const float* Wp = (const float*)d_in[5];
    const float* bp = (const float*)d_in[6];
    float* out = (float*)d_out;

    cudaFuncSetAttribute(hetero_kernel,
                         cudaFuncAttributeMaxDynamicSharedMemorySize, HET_SMEM);

    convert_kernel<<<2048, 256>>>(u, Wp);
    hetero_kernel<<<GEMM_CTAS + CONV_CTAS, 256, HET_SMEM>>>(u, w1, b1, w2, b2, bp, out);
}

// round 8
// speedup vs baseline: 1.0569x; 1.0569x over previous
#include <cuda_runtime.h>
#include <cuda_fp16.h>
#include <cstdint>

#define L_SEQ 4096
#define D_DIM 1024
#define BATCH 4
#define M_TOT 16384

// scratch
__device__ float  g_uproj[(size_t)M_TOT * D_DIM];   // 64 MB
// tiled fp16: [tile][kc][row 128][64B], 8KB per (tile,kc) block, swizzled
__device__ __align__(16) __half g_Uh[(size_t)M_TOT * D_DIM];  // 32 MB
__device__ __align__(16) __half g_Wh[(size_t)D_DIM * D_DIM];  // 2 MB

__device__ __forceinline__ float silu_f(float x) {
    return x / (1.0f + __expf(-x));
}

__device__ __forceinline__ uint32_t smem_u32(const void* p) {
    uint32_t a;
    asm("{ .reg .u64 t; cvta.to.shared.u64 t, %1; cvt.u32.u64 %0, t; }"
        : "=r"(a) : "l"(p));
    return a;
}

// ---------------------------------------------------------------------------
// Kernel 0: convert U, Wp to fp16 in tiled+swizzled layout.
// ---------------------------------------------------------------------------
#define NCH_U (M_TOT * 128)     // 16B-chunks for U: 16384 rows * 128
#define NCH_W (D_DIM * 128)

__global__ void __launch_bounds__(256)
convert_kernel(const float* __restrict__ U, const float* __restrict__ Wp)
{
    const int stride = gridDim.x * blockDim.x;
    for (int i = blockIdx.x * blockDim.x + threadIdx.x;
         i < NCH_U + NCH_W; i += stride) {
        int j; const float* src; __half* dstbase;
        if (i < NCH_U) { j = i; src = U; dstbase = g_Uh; }
        else           { j = i - NCH_U; src = Wp; dstbase = g_Wh; }
        const int c    = j & 3;
        const int r    = (j >> 2) & 127;
        const int kc   = (j >> 9) & 31;
        const int tile = j >> 14;
        const int m    = tile * 128 + r;
        const float4* s = (const float4*)(src + (size_t)m * D_DIM + kc * 32 + c * 8);
        float4 v0 = s[0], v1 = s[1];
        __half2 h0 = __floats2half2_rn(v0.x, v0.y);
        __half2 h1 = __floats2half2_rn(v0.z, v0.w);
        __half2 h2 = __floats2half2_rn(v1.x, v1.y);
        __half2 h3 = __floats2half2_rn(v1.z, v1.w);
        uint4 o;
        o.x = *(const uint32_t*)&h0; o.y = *(const uint32_t*)&h1;
        o.z = *(const uint32_t*)&h2; o.w = *(const uint32_t*)&h3;
        const int csw = c ^ ((r >> 1) & 3);
        const size_t half_off = ((size_t)(tile * 32 + kc) << 12)
                              + (size_t)r * 32 + csw * 8;
        *(uint4*)(dstbase + half_off) = o;
    }
}

// ---------------------------------------------------------------------------
// Heterogeneous kernel: bids [0,1024) = GEMM 128x128 tiles (tensor pipe),
// bids [1024,3072) = conv CTAs (fma/lds pipes).
// GEMM staging: 5-stage cp.async.bulk ring, prefetch distance 4,
// issue-before-wait each iteration.
// ---------------------------------------------------------------------------
#define GEMM_CTAS 1024
#define CONV_CTAS 2048
#define STAGE_SZ 16384          // A 8KB + B 8KB
#define NSTAGE 5
#define PREF 4                  // prefetch distance
#define SM_MBAR  (NSTAGE * STAGE_SZ)   // 81920, 5 mbarriers
#define HET_SMEM 98304          // conv needs 96KB

#define MBAR_INIT(mbar, cnt) \
    asm volatile("mbarrier.init.shared.b64 [%0], %1;" \
                 :: "r"((uint32_t)(mbar)), "r"((uint32_t)(cnt)) : "memory")
#define MBAR_EXPECT_TX(mbar, bytes) \
    asm volatile("mbarrier.arrive.expect_tx.shared.b64 _, [%0], %1;" \
                 :: "r"((uint32_t)(mbar)), "r"((uint32_t)(bytes)) : "memory")
#define MBAR_WAIT(mbar, ph) do { \
    uint32_t _m = (uint32_t)(mbar); uint32_t _p = (uint32_t)(ph); \
    asm volatile("{\n\t.reg .pred P1;\n\t" \
        "W_%=:\n\t" \
        "mbarrier.try_wait.parity.acquire.cta.shared::cta.b64 P1, [%0], %1, 0x989680;\n\t" \
        "@P1 bra.uni D_%=;\n\t" \
        "bra.uni W_%=;\n\t" \
        "D_%=:\n\t}" :: "r"(_m), "r"(_p) : "memory"); \
} while (0)

__device__ __forceinline__ void bulk_cp(uint32_t dst, const void* src,
                                        uint32_t bytes, uint32_t mbar) {
    asm volatile(
        "cp.async.bulk.shared::cta.global.mbarrier::complete_tx::bytes "
        "[%0], [%1], %2, [%3];"
        :: "r"(dst), "l"(__cvta_generic_to_global(src)), "r"(bytes), "r"(mbar)
        : "memory");
}

__device__ __forceinline__ void ldmatrix4(uint32_t* r, uint32_t addr) {
    asm volatile("ldmatrix.sync.aligned.m8n8.x4.shared.b16 {%0,%1,%2,%3}, [%4];"
                 : "=r"(r[0]), "=r"(r[1]), "=r"(r[2]), "=r"(r[3]) : "r"(addr));
}

__device__ __forceinline__ void mma16816(float* c, const uint32_t* a,
                                         uint32_t b0, uint32_t b1) {
    asm volatile(
        "mma.sync.aligned.m16n8k16.row.col.f32.f16.f16.f32 "
        "{%0,%1,%2,%3}, {%4,%5,%6,%7}, {%8,%9}, {%0,%1,%2,%3};"
        : "+f"(c[0]), "+f"(c[1]), "+f"(c[2]), "+f"(c[3])
        : "r"(a[0]), "r"(a[1]), "r"(a[2]), "r"(a[3]), "r"(b0), "r"(b1));
}

// conv geometry
#define CLT 128
#define CP  32
#define CHROWS (CLT + 128)

typedef unsigned long long ull;

__device__ __forceinline__ void ffma2(ull& d, ull a, ull b) {
    asm("fma.rn.f32x2 %0, %1, %2, %0;" : "+l"(d) : "l"(a), "l"(b));
}
__device__ __forceinline__ float2 unpack2(ull v) {
    float2 r;
    asm("mov.b64 {%0,%1}, %2;" : "=f"(r.x), "=f"(r.y) : "l"(v));
    return r;
}

__device__ void gemm_part(char* sm, const float* __restrict__ bp)
{
    const uint32_t sbase = smem_u32(sm);
    const uint32_t mb    = sbase + SM_MBAR;
    const int tid  = threadIdx.x;
    const int lane = tid & 31;
    const int warp = tid >> 5;
    const int wm = warp & 3;      // 0..3  M 32-row slab
    const int wn = warp >> 2;     // 0..1  N 64-col slab

    const int t      = blockIdx.x;
    const int tile_m = t >> 3;
    const int tile_n = t & 7;
    const int m0 = tile_m * 128;
    const int n0 = tile_n * 128;

    float c[2][8][4];
    #pragma unroll
    for (int i = 0; i < 2; i++)
        #pragma unroll
        for (int j = 0; j < 8; j++)
            #pragma unroll
            for (int r = 0; r < 4; r++) c[i][j][r] = 0.0f;

    // precompute per-lane ldmatrix offsets (swizzled, row stride 64B)
    int offA[2][2], offB[4][2];
    {
        const int c0a = (lane >> 4) & 1;
        const int c0b = (lane >> 3) & 1;
        #pragma unroll
        for (int mt = 0; mt < 2; mt++) {
            int rA = wm * 32 + mt * 16 + (lane & 7) + ((lane >> 3) & 1) * 8;
            int sw = (rA >> 1) & 3;
            #pragma unroll
            for (int kk = 0; kk < 2; kk++)
                offA[mt][kk] = rA * 64 + (((c0a | (kk << 1)) ^ sw) << 4);
        }
        #pragma unroll
        for (int bh = 0; bh < 4; bh++) {
            int rB = wn * 64 + bh * 16 + (lane & 7) + ((lane >> 4) & 1) * 8;
            int sw = (rB >> 1) & 3;
            #pragma unroll
            for (int kk = 0; kk < 2; kk++)
                offB[bh][kk] = 8192 + rB * 64 + (((c0b | (kk << 1)) ^ sw) << 4);
        }
    }

    const char* Abase = (const char*)g_Uh + (size_t)tile_m * 32 * 8192;
    const char* Bbase = (const char*)g_Wh + (size_t)tile_n * 32 * 8192;

    if (tid == 0) {
        #pragma unroll
        for (int i = 0; i < NSTAGE; i++) MBAR_INIT(mb + i * 8, 1);
        asm volatile("fence.proxy.async.shared::cta;" ::: "memory");
        #pragma unroll
        for (int k0 = 0; k0 < PREF; k0++) {
            MBAR_EXPECT_TX(mb + k0 * 8, STAGE_SZ);
            bulk_cp(sbase + k0 * STAGE_SZ,        Abase + (size_t)k0 * 8192,
                    8192, mb + k0 * 8);
            bulk_cp(sbase + k0 * STAGE_SZ + 8192, Bbase + (size_t)k0 * 8192,
                    8192, mb + k0 * 8);
        }
    }

    for (int kc = 0; kc < 32; kc++) {
        const int s = kc % NSTAGE;
        // all warps done with kc-1 => slot (kc+PREF)%5 == (kc-1)%5 reusable
        __syncthreads();
        if (tid == 0 && kc + PREF < 32) {
            const int slot = (kc + PREF) % NSTAGE;
            asm volatile("fence.proxy.async.shared::cta;" ::: "memory");
            MBAR_EXPECT_TX(mb + slot * 8, STAGE_SZ);
            bulk_cp(sbase + slot * STAGE_SZ,
                    Abase + (size_t)(kc + PREF) * 8192, 8192, mb + slot * 8);
            bulk_cp(sbase + slot * STAGE_SZ + 8192,
                    Bbase + (size_t)(kc + PREF) * 8192, 8192, mb + slot * 8);
        }
        MBAR_WAIT(mb + s * 8, (kc / NSTAGE) & 1);

        const uint32_t stage = sbase + s * STAGE_SZ;
        #pragma unroll
        for (int kk = 0; kk < 2; kk++) {
            uint32_t ar[2][4];
            #pragma unroll
            for (int mt = 0; mt < 2; mt++)
                ldmatrix4(ar[mt], stage + offA[mt][kk]);
            #pragma unroll
            for (int bh = 0; bh < 4; bh++) {
                uint32_t br[4];
                ldmatrix4(br, stage + offB[bh][kk]);
                #pragma unroll
                for (int mt = 0; mt < 2; mt++) {
                    mma16816(c[mt][2 * bh + 0], ar[mt], br[0], br[1]);
                    mma16816(c[mt][2 * bh + 1], ar[mt], br[2], br[3]);
                }
            }
        }
    }

    const int g  = lane >> 2;
    const int tq = lane & 3;
    #pragma unroll
    for (int mt = 0; mt < 2; mt++) {
        const int row = m0 + wm * 32 + mt * 16 + g;
        #pragma unroll
        for (int nt = 0; nt < 8; nt++) {
            const int col = n0 + wn * 64 + nt * 8 + tq * 2;
            float2 bb = *(const float2*)(bp + col);
            float2 v0 = make_float2(silu_f(c[mt][nt][0] + bb.x),
                                    silu_f(c[mt][nt][1] + bb.y));
            float2 v1 = make_float2(silu_f(c[mt][nt][2] + bb.x),
                                    silu_f(c[mt][nt][3] + bb.y));
            *(float2*)(g_uproj + (size_t)row * D_DIM + col)       = v0;
            *(float2*)(g_uproj + (size_t)(row + 8) * D_DIM + col) = v1;
        }
    }
}

__device__ void conv_part(char* smc,
                          const float* __restrict__ u,
                          const float* __restrict__ w1,
                          const float* __restrict__ b1,
                          const float* __restrict__ w2,
                          const float* __restrict__ b2,
                          float* __restrict__ out)
{
    float2* h_s  = (float2*)smc;                              // [256][32]
    float2* w2_s = (float2*)(smc + CHROWS * CP * 8);          // [128][32]

    const int tid = threadIdx.x;
    const int c   = tid & 31;
    const int yy  = tid >> 5;

    const int idx   = blockIdx.x - GEMM_CTAS;
    const int chunk = idx & 15;
    const int lt    = (idx >> 4) & 31;
    const int bb    = idx >> 9;
    const int tile_start = lt * CLT;
    const int p = chunk * CP + c;

    const float2* uf2  = (const float2*)u + (size_t)bb * L_SEQ * 512;
    const float2* w1f2 = (const float2*)w1;
    const float2* w2f2 = (const float2*)w2;

    #pragma unroll
    for (int i = tid; i < 128 * CP; i += 256) {
        int j = i >> 5, cc = i & 31;
        w2_s[j * CP + cc] = w2f2[(size_t)j * 512 + chunk * CP + cc];
    }

    const float2 w1_0 = w1f2[0 * 512 + p];
    const float2 w1_1 = w1f2[1 * 512 + p];
    const float2 w1_2 = w1f2[2 * 512 + p];
    const float2 b1c  = ((const float2*)b1)[p];

    for (int i = tid; i < CHROWS * CP; i += 256) {
        int hl = i >> 5;
        int l  = tile_start - 127 + hl;
        float2 hv = make_float2(0.0f, 0.0f);
        if (l >= 0 && l < L_SEQ) {
            float2 x2 = uf2[(size_t)l * 512 + p];
            float2 x1 = (l >= 1) ? uf2[(size_t)(l - 1) * 512 + p] : make_float2(0.f, 0.f);
            float2 x0 = (l >= 2) ? uf2[(size_t)(l - 2) * 512 + p] : make_float2(0.f, 0.f);
            float vx = fmaf(x0.x, w1_0.x, fmaf(x1.x, w1_1.x, fmaf(x2.x, w1_2.x, b1c.x)));
            float vy = fmaf(x0.y, w1_0.y, fmaf(x1.y, w1_1.y, fmaf(x2.y, w1_2.y, b1c.y)));
            hv.x = silu_f(vx);
            hv.y = silu_f(vy);
        }
        h_s[hl * CP + c] = hv;
    }
    __syncthreads();

    const int base = yy * 16;
    ull acc[16], win[16];
    #pragma unroll
    for (int r = 0; r < 16; r++) {
        acc[r] = 0ULL;
        win[r] = *(const ull*)&h_s[(base + r) * CP + c];
    }
    #pragma unroll 8
    for (int j = 0; j < 128; j++) {
        ull w = *(const ull*)&w2_s[j * CP + c];
        #pragma unroll
        for (int r = 0; r < 16; r++)
            ffma2(acc[r], win[(j + r) & 15], w);
        win[j & 15] = *(const ull*)&h_s[(base + j + 16) * CP + c];
    }

    const float2 b2c = ((const float2*)b2)[p];
    float2* opf2 = (float2*)out + ((size_t)bb * L_SEQ + tile_start) * 512 + p;

    #pragma unroll
    for (int r = 0; r < 16; r++) {
        float2 a = unpack2(acc[r]);
        int lo   = base + r;
        float2 y;
        y.x = a.x + b2c.x;
        y.y = a.y + b2c.y;
        opf2[(size_t)lo * 512] = y;
    }
}

__global__ void __launch_bounds__(256, 2)
hetero_kernel(const float* __restrict__ u,
              const float* __restrict__ w1,
              const float* __restrict__ b1,
              const float* __restrict__ w2,
              const float* __restrict__ b2,
              const float* __restrict__ bp,
              float* __restrict__ out)
{
    extern __shared__ __align__(128) char sm[];
    if (blockIdx.x < GEMM_CTAS)
        gemm_part(sm, bp);
    else
        conv_part(sm, u, w1, b1, w2, b2, out);
}

// ---------------------------------------------------------------------------
// Final: out *= uproj (in place)
// ---------------------------------------------------------------------------
__global__ void __launch_bounds__(256)
mult_kernel(float* __restrict__ out)
{
    const size_t n4 = (size_t)M_TOT * D_DIM / 4;
    const size_t stride = (size_t)gridDim.x * blockDim.x;
    for (size_t i = (size_t)blockIdx.x * blockDim.x + threadIdx.x;
         i < n4; i += stride) {
        float4 o = ((const float4*)out)[i];
        float4 p = ((const float4*)g_uproj)[i];
        o.x *= p.x; o.y *= p.y; o.z *= p.z; o.w *= p.w;
        ((float4*)out)[i] = o;
    }
}

// ---------------------------------------------------------------------------
extern "C" void kernel_launch(void* const* d_in, const int* in_sizes, int n_in,
                              void* d_out, int out_size)
{
    const float* u  = (const float*)d_in[0];
    const float* w1 = (const float*)d_in[1];
    const float* b1 = (const float*)d_in[2];
    const float* w2 = (const float*)d_in[3];
    const float* b2 = (const float*)d_in[4];
    const float* Wp = (const float*)d_in[5];
    const float* bp = (const float*)d_in[6];
    float* out = (float*)d_out;

    cudaFuncSetAttribute(hetero_kernel,
                         cudaFuncAttributeMaxDynamicSharedMemorySize, HET_SMEM);

    convert_kernel<<<2048, 256>>>(u, Wp);
    hetero_kernel<<<GEMM_CTAS + CONV_CTAS, 256, HET_SMEM>>>(u, w1, b1, w2, b2, bp, out);
    mult_kernel<<<2048, 256>>>(out);
}

// round 9
// speedup vs baseline: 1.4079x; 1.3322x over previous
#include <cuda_runtime.h>
#include <cuda_fp16.h>
#include <cstdint>

#define L_SEQ 4096
#define D_DIM 1024
#define BATCH 4
#define M_TOT 16384

// scratch
__device__ float  g_uproj[(size_t)M_TOT * D_DIM];   // 64 MB
// g_Uh tiled: [tile_m(128)][kc(32)][row 128][64B] -> 8KB blocks, swizzled
// g_Wh tiled: [tile_n(16)][kc(32)][row 64][64B]   -> 4KB blocks, swizzled
__device__ __align__(16) __half g_Uh[(size_t)M_TOT * D_DIM];  // 32 MB
__device__ __align__(16) __half g_Wh[(size_t)D_DIM * D_DIM];  // 2 MB

__device__ __forceinline__ float silu_f(float x) {
    return x / (1.0f + __expf(-x));
}

__device__ __forceinline__ uint32_t smem_u32(const void* p) {
    uint32_t a;
    asm("{ .reg .u64 t; cvta.to.shared.u64 t, %1; cvt.u32.u64 %0, t; }"
        : "=r"(a) : "l"(p));
    return a;
}

// ---------------------------------------------------------------------------
// Kernel 0: convert U, Wp to fp16 tiled+swizzled.
// ---------------------------------------------------------------------------
#define NCH_U (M_TOT * 128)
#define NCH_W (D_DIM * 128)

__global__ void __launch_bounds__(256)
convert_kernel(const float* __restrict__ U, const float* __restrict__ Wp)
{
    const int stride = gridDim.x * blockDim.x;
    const int tid0 = blockIdx.x * blockDim.x + threadIdx.x;
    // U: 128-row tiles
    for (int j = tid0; j < NCH_U; j += stride) {
        const int c    = j & 3;
        const int r    = (j >> 2) & 127;
        const int kc   = (j >> 9) & 31;
        const int tile = j >> 14;
        const int m    = tile * 128 + r;
        const float4* s = (const float4*)(U + (size_t)m * D_DIM + kc * 32 + c * 8);
        float4 v0 = s[0], v1 = s[1];
        __half2 h0 = __floats2half2_rn(v0.x, v0.y);
        __half2 h1 = __floats2half2_rn(v0.z, v0.w);
        __half2 h2 = __floats2half2_rn(v1.x, v1.y);
        __half2 h3 = __floats2half2_rn(v1.z, v1.w);
        uint4 o;
        o.x = *(const uint32_t*)&h0; o.y = *(const uint32_t*)&h1;
        o.z = *(const uint32_t*)&h2; o.w = *(const uint32_t*)&h3;
        const int csw = c ^ ((r >> 1) & 3);
        const size_t off = ((size_t)(tile * 32 + kc) << 12) + (size_t)r * 32 + csw * 8;
        *(uint4*)(g_Uh + off) = o;
    }
    // W: 64-row tiles (4KB blocks)
    for (int j = tid0; j < NCH_W; j += stride) {
        const int c    = j & 3;
        const int r    = (j >> 2) & 63;
        const int kc   = (j >> 8) & 31;
        const int tile = j >> 13;
        const int n    = tile * 64 + r;
        const float4* s = (const float4*)(Wp + (size_t)n * D_DIM + kc * 32 + c * 8);
        float4 v0 = s[0], v1 = s[1];
        __half2 h0 = __floats2half2_rn(v0.x, v0.y);
        __half2 h1 = __floats2half2_rn(v0.z, v0.w);
        __half2 h2 = __floats2half2_rn(v1.x, v1.y);
        __half2 h3 = __floats2half2_rn(v1.z, v1.w);
        uint4 o;
        o.x = *(const uint32_t*)&h0; o.y = *(const uint32_t*)&h1;
        o.z = *(const uint32_t*)&h2; o.w = *(const uint32_t*)&h3;
        const int csw = c ^ ((r >> 1) & 3);
        const size_t off = ((size_t)(tile * 32 + kc) << 11) + (size_t)r * 32 + csw * 8;
        *(uint4*)(g_Wh + off) = o;
    }
}

// ---------------------------------------------------------------------------
// Heterogeneous kernel, 4 CTAs/SM (32 warps/SM):
//  bids [0,2048)      = GEMM 128x64 tiles, 8 warps of 32x32, <=64 regs
//  bids [2048,6144)   = conv CTAs, CP=16, 48KB smem
// ---------------------------------------------------------------------------
#define GEMM_CTAS 2048
#define CONV_CTAS 4096
#define STAGE_SZ 12288          // A 8KB + B 4KB
#define NSTAGE 3
#define PREF 2
#define SM_MBAR  (NSTAGE * STAGE_SZ)   // 36864
#define HET_SMEM 49152

#define MBAR_INIT(mbar, cnt) \
    asm volatile("mbarrier.init.shared.b64 [%0], %1;" \
                 :: "r"((uint32_t)(mbar)), "r"((uint32_t)(cnt)) : "memory")
#define MBAR_EXPECT_TX(mbar, bytes) \
    asm volatile("mbarrier.arrive.expect_tx.shared.b64 _, [%0], %1;" \
                 :: "r"((uint32_t)(mbar)), "r"((uint32_t)(bytes)) : "memory")
#define MBAR_WAIT(mbar, ph) do { \
    uint32_t _m = (uint32_t)(mbar); uint32_t _p = (uint32_t)(ph); \
    asm volatile("{\n\t.reg .pred P1;\n\t" \
        "W_%=:\n\t" \
        "mbarrier.try_wait.parity.acquire.cta.shared::cta.b64 P1, [%0], %1, 0x989680;\n\t" \
        "@P1 bra.uni D_%=;\n\t" \
        "bra.uni W_%=;\n\t" \
        "D_%=:\n\t}" :: "r"(_m), "r"(_p) : "memory"); \
} while (0)

__device__ __forceinline__ void bulk_cp(uint32_t dst, const void* src,
                                        uint32_t bytes, uint32_t mbar) {
    asm volatile(
        "cp.async.bulk.shared::cta.global.mbarrier::complete_tx::bytes "
        "[%0], [%1], %2, [%3];"
        :: "r"(dst), "l"(__cvta_generic_to_global(src)), "r"(bytes), "r"(mbar)
        : "memory");
}

__device__ __forceinline__ void ldmatrix4(uint32_t* r, uint32_t addr) {
    asm volatile("ldmatrix.sync.aligned.m8n8.x4.shared.b16 {%0,%1,%2,%3}, [%4];"
                 : "=r"(r[0]), "=r"(r[1]), "=r"(r[2]), "=r"(r[3]) : "r"(addr));
}

__device__ __forceinline__ void mma16816(float* c, const uint32_t* a,
                                         uint32_t b0, uint32_t b1) {
    asm volatile(
        "mma.sync.aligned.m16n8k16.row.col.f32.f16.f16.f32 "
        "{%0,%1,%2,%3}, {%4,%5,%6,%7}, {%8,%9}, {%0,%1,%2,%3};"
        : "+f"(c[0]), "+f"(c[1]), "+f"(c[2]), "+f"(c[3])
        : "r"(a[0]), "r"(a[1]), "r"(a[2]), "r"(a[3]), "r"(b0), "r"(b1));
}

// conv geometry: CP=16 channel pairs (32 channels), 16 workers x 8 outputs
#define CLT 128
#define CP  16
#define CHROWS (CLT + 128)

typedef unsigned long long ull;

__device__ __forceinline__ void ffma2(ull& d, ull a, ull b) {
    asm("fma.rn.f32x2 %0, %1, %2, %0;" : "+l"(d) : "l"(a), "l"(b));
}
__device__ __forceinline__ float2 unpack2(ull v) {
    float2 r;
    asm("mov.b64 {%0,%1}, %2;" : "=f"(r.x), "=f"(r.y) : "l"(v));
    return r;
}

__device__ void gemm_part(char* sm, const float* __restrict__ bp)
{
    const uint32_t sbase = smem_u32(sm);
    const uint32_t mb    = sbase + SM_MBAR;
    const int tid  = threadIdx.x;
    const int lane = tid & 31;
    const int warp = tid >> 5;
    const int wm = warp >> 1;     // 0..3  M 32-row slab
    const int wn = warp & 1;      // 0..1  N 32-col slab

    const int t      = blockIdx.x;
    const int tile_m = t >> 4;    // 0..127
    const int tile_n = t & 15;    // 0..15
    const int m0 = tile_m * 128;
    const int n0 = tile_n * 64;

    float c[2][4][4];
    #pragma unroll
    for (int i = 0; i < 2; i++)
        #pragma unroll
        for (int j = 0; j < 4; j++)
            #pragma unroll
            for (int r = 0; r < 4; r++) c[i][j][r] = 0.0f;

    // ldmatrix per-lane offsets (swizzled, 64B rows)
    int offA[2][2], offB[2][2];
    {
        const int c0a = (lane >> 4) & 1;
        const int c0b = (lane >> 3) & 1;
        #pragma unroll
        for (int mt = 0; mt < 2; mt++) {
            int rA = wm * 32 + mt * 16 + (lane & 7) + ((lane >> 3) & 1) * 8;
            int sw = (rA >> 1) & 3;
            #pragma unroll
            for (int kk = 0; kk < 2; kk++)
                offA[mt][kk] = rA * 64 + (((c0a | (kk << 1)) ^ sw) << 4);
        }
        #pragma unroll
        for (int bh = 0; bh < 2; bh++) {
            int rB = wn * 32 + bh * 16 + (lane & 7) + ((lane >> 4) & 1) * 8;
            int sw = (rB >> 1) & 3;
            #pragma unroll
            for (int kk = 0; kk < 2; kk++)
                offB[bh][kk] = 8192 + rB * 64 + (((c0b | (kk << 1)) ^ sw) << 4);
        }
    }

    const char* Abase = (const char*)g_Uh + (size_t)tile_m * 32 * 8192;
    const char* Bbase = (const char*)g_Wh + (size_t)tile_n * 32 * 4096;

    if (tid == 0) {
        #pragma unroll
        for (int i = 0; i < NSTAGE; i++) MBAR_INIT(mb + i * 8, 1);
        asm volatile("fence.proxy.async.shared::cta;" ::: "memory");
        #pragma unroll
        for (int k0 = 0; k0 < PREF; k0++) {
            MBAR_EXPECT_TX(mb + k0 * 8, STAGE_SZ);
            bulk_cp(sbase + k0 * STAGE_SZ,        Abase + (size_t)k0 * 8192,
                    8192, mb + k0 * 8);
            bulk_cp(sbase + k0 * STAGE_SZ + 8192, Bbase + (size_t)k0 * 4096,
                    4096, mb + k0 * 8);
        }
    }

    for (int kc = 0; kc < 32; kc++) {
        const int s = kc % NSTAGE;
        __syncthreads();
        if (tid == 0 && kc + PREF < 32) {
            const int slot = (kc + PREF) % NSTAGE;
            asm volatile("fence.proxy.async.shared::cta;" ::: "memory");
            MBAR_EXPECT_TX(mb + slot * 8, STAGE_SZ);
            bulk_cp(sbase + slot * STAGE_SZ,
                    Abase + (size_t)(kc + PREF) * 8192, 8192, mb + slot * 8);
            bulk_cp(sbase + slot * STAGE_SZ + 8192,
                    Bbase + (size_t)(kc + PREF) * 4096, 4096, mb + slot * 8);
        }
        MBAR_WAIT(mb + s * 8, (kc / NSTAGE) & 1);

        const uint32_t stage = sbase + s * STAGE_SZ;
        #pragma unroll
        for (int kk = 0; kk < 2; kk++) {
            uint32_t ar[2][4];
            #pragma unroll
            for (int mt = 0; mt < 2; mt++)
                ldmatrix4(ar[mt], stage + offA[mt][kk]);
            #pragma unroll
            for (int bh = 0; bh < 2; bh++) {
                uint32_t br[4];
                ldmatrix4(br, stage + offB[bh][kk]);
                #pragma unroll
                for (int mt = 0; mt < 2; mt++) {
                    mma16816(c[mt][2 * bh + 0], ar[mt], br[0], br[1]);
                    mma16816(c[mt][2 * bh + 1], ar[mt], br[2], br[3]);
                }
            }
        }
    }

    const int g  = lane >> 2;
    const int tq = lane & 3;
    #pragma unroll
    for (int mt = 0; mt < 2; mt++) {
        const int row = m0 + wm * 32 + mt * 16 + g;
        #pragma unroll
        for (int nt = 0; nt < 4; nt++) {
            const int col = n0 + wn * 32 + nt * 8 + tq * 2;
            float2 bb = *(const float2*)(bp + col);
            float2 v0 = make_float2(silu_f(c[mt][nt][0] + bb.x),
                                    silu_f(c[mt][nt][1] + bb.y));
            float2 v1 = make_float2(silu_f(c[mt][nt][2] + bb.x),
                                    silu_f(c[mt][nt][3] + bb.y));
            *(float2*)(g_uproj + (size_t)row * D_DIM + col)       = v0;
            *(float2*)(g_uproj + (size_t)(row + 8) * D_DIM + col) = v1;
        }
    }
}

__device__ void conv_part(char* smc,
                          const float* __restrict__ u,
                          const float* __restrict__ w1,
                          const float* __restrict__ b1,
                          const float* __restrict__ w2,
                          const float* __restrict__ b2,
                          float* __restrict__ out)
{
    float2* h_s  = (float2*)smc;                              // [256][16]
    float2* w2_s = (float2*)(smc + CHROWS * CP * 8);          // [128][16]

    const int tid = threadIdx.x;
    const int c   = tid & 15;       // channel pair lane 0..15
    const int yy  = tid >> 4;       // worker 0..15

    const int idx   = blockIdx.x - GEMM_CTAS;
    const int chunk = idx & 31;            // 32-channel group 0..31
    const int lt    = (idx >> 5) & 31;
    const int bb    = idx >> 10;
    const int tile_start = lt * CLT;
    const int p = chunk * CP + c;          // pair index 0..511

    const float2* uf2  = (const float2*)u + (size_t)bb * L_SEQ * 512;
    const float2* w1f2 = (const float2*)w1;
    const float2* w2f2 = (const float2*)w2;

    #pragma unroll
    for (int i = tid; i < 128 * CP; i += 256) {
        int j = i >> 4, cc = i & 15;
        w2_s[j * CP + cc] = w2f2[(size_t)j * 512 + chunk * CP + cc];
    }

    const float2 w1_0 = w1f2[0 * 512 + p];
    const float2 w1_1 = w1f2[1 * 512 + p];
    const float2 w1_2 = w1f2[2 * 512 + p];
    const float2 b1c  = ((const float2*)b1)[p];

    // (i & 15) == c for all iterations (stride 256), so w1 regs match
    for (int i = tid; i < CHROWS * CP; i += 256) {
        int hl = i >> 4;
        int l  = tile_start - 127 + hl;
        float2 hv = make_float2(0.0f, 0.0f);
        if (l >= 0 && l < L_SEQ) {
            float2 x2 = uf2[(size_t)l * 512 + p];
            float2 x1 = (l >= 1) ? uf2[(size_t)(l - 1) * 512 + p] : make_float2(0.f, 0.f);
            float2 x0 = (l >= 2) ? uf2[(size_t)(l - 2) * 512 + p] : make_float2(0.f, 0.f);
            float vx = fmaf(x0.x, w1_0.x, fmaf(x1.x, w1_1.x, fmaf(x2.x, w1_2.x, b1c.x)));
            float vy = fmaf(x0.y, w1_0.y, fmaf(x1.y, w1_1.y, fmaf(x2.y, w1_2.y, b1c.y)));
            hv.x = silu_f(vx);
            hv.y = silu_f(vy);
        }
        h_s[hl * CP + c] = hv;
    }
    __syncthreads();

    const int base = yy * 8;    // 16 workers x 8 outputs = 128
    ull acc[8], win[8];
    #pragma unroll
    for (int r = 0; r < 8; r++) {
        acc[r] = 0ULL;
        win[r] = *(const ull*)&h_s[(base + r) * CP + c];
    }
    #pragma unroll 8
    for (int j = 0; j < 128; j++) {
        ull w = *(const ull*)&w2_s[j * CP + c];
        #pragma unroll
        for (int r = 0; r < 8; r++)
            ffma2(acc[r], win[(j + r) & 7], w);
        // max row: 120 + 127 + 8 = 255, in bounds
        win[j & 7] = *(const ull*)&h_s[(base + j + 8) * CP + c];
    }

    const float2 b2c = ((const float2*)b2)[p];
    float2* opf2 = (float2*)out + ((size_t)bb * L_SEQ + tile_start) * 512 + p;

    #pragma unroll
    for (int r = 0; r < 8; r++) {
        float2 a = unpack2(acc[r]);
        int lo   = base + r;
        float2 y;
        y.x = a.x + b2c.x;
        y.y = a.y + b2c.y;
        opf2[(size_t)lo * 512] = y;
    }
}

__global__ void __launch_bounds__(256, 4)
hetero_kernel(const float* __restrict__ u,
              const float* __restrict__ w1,
              const float* __restrict__ b1,
              const float* __restrict__ w2,
              const float* __restrict__ b2,
              const float* __restrict__ bp,
              float* __restrict__ out)
{
    extern __shared__ __align__(128) char sm[];
    if (blockIdx.x < GEMM_CTAS)
        gemm_part(sm, bp);
    else
        conv_part(sm, u, w1, b1, w2, b2, out);
}

// ---------------------------------------------------------------------------
// Final: out *= uproj (in place)
// ---------------------------------------------------------------------------
__global__ void __launch_bounds__(256)
mult_kernel(float* __restrict__ out)
{
    const size_t n4 = (size_t)M_TOT * D_DIM / 4;
    const size_t stride = (size_t)gridDim.x * blockDim.x;
    for (size_t i = (size_t)blockIdx.x * blockDim.x + threadIdx.x;
         i < n4; i += stride) {
        float4 o = ((const float4*)out)[i];
        float4 p = ((const float4*)g_uproj)[i];
        o.x *= p.x; o.y *= p.y; o.z *= p.z; o.w *= p.w;
        ((float4*)out)[i] = o;
    }
}

// ---------------------------------------------------------------------------
extern "C" void kernel_launch(void* const* d_in, const int* in_sizes, int n_in,
                              void* d_out, int out_size)
{
    const float* u  = (const float*)d_in[0];
    const float* w1 = (const float*)d_in[1];
    const float* b1 = (const float*)d_in[2];
    const float* w2 = (const float*)d_in[3];
    const float* b2 = (const float*)d_in[4];
    const float* Wp = (const float*)d_in[5];
    const float* bp = (const float*)d_in[6];
    float* out = (float*)d_out;

    cudaFuncSetAttribute(hetero_kernel,
                         cudaFuncAttributeMaxDynamicSharedMemorySize, HET_SMEM);

    convert_kernel<<<2048, 256>>>(u, Wp);
    hetero_kernel<<<GEMM_CTAS + CONV_CTAS, 256, HET_SMEM>>>(u, w1, b1, w2, b2, bp, out);
    mult_kernel<<<2048, 256>>>(out);
}